// round 6
// baseline (speedup 1.0000x reference)
#include <cuda_runtime.h>
#include <cuda_fp16.h>
#include <cstdint>
#include <cstddef>

// ---------------------------------------------------------------------------
// DeepCausalModel. fp16 mma.m16n8k16 path (tcgen05 blocked by compute_103).
// CTA 256x128, warp 64x64, BK=64, SW128 swizzle + ldmatrix.x4, 4-stage
// cp.async, 1 barrier/ktile, register double-buffered fragments.
// Experts gathered by treatment. Launch order puts trunk GEMM2 at index 3
// (the launch ncu profiles).
// ---------------------------------------------------------------------------

#define NROWS 65536

constexpr size_t OFF_XH  = 0;                                // [N,512]
constexpr size_t OFF_WX0 = OFF_XH  + (size_t)NROWS * 512;    // [2048,512] (T)
constexpr size_t OFF_WX1 = OFF_WX0 + (size_t)512 * 2048;     // [2048,2048]
constexpr size_t OFF_WX2 = OFF_WX1 + (size_t)2048 * 2048;    // [512,2048]
constexpr size_t OFF_WY0 = OFF_WX2 + (size_t)2048 * 512;     // 2x [1024,512]
constexpr size_t OFF_WY1 = OFF_WY0 + (size_t)2 * 512 * 1024; // 2x [512,1024]
constexpr size_t OFF_H0  = OFF_WY1 + (size_t)2 * 1024 * 512; // [N,2048]
constexpr size_t OFF_H1  = OFF_H0  + (size_t)NROWS * 2048;   // [N,2048]
constexpr size_t OFF_XEH = OFF_H1  + (size_t)NROWS * 2048;   // [N,512]
constexpr size_t SCR_TOTAL = OFF_XEH + (size_t)NROWS * 512;
constexpr size_t OFF_G0A = OFF_H0;
constexpr size_t OFF_G0B = OFF_H0 + (size_t)NROWS * 1024;
constexpr size_t OFF_G1A = OFF_H1;
constexpr size_t OFF_G1B = OFF_H1 + (size_t)NROWS * 512;

__device__ __half g_scratch[SCR_TOTAL];
__device__ int    g_idx0[NROWS];
__device__ int    g_idx1[NROWS];
__device__ int    g_meta[8];

// ---------------------------------------------------------------------------
__global__ void cvt_half_kernel(const float4* __restrict__ in,
                                __half* __restrict__ out, int n8) {
    int i = blockIdx.x * blockDim.x + threadIdx.x;
    if (i < n8) {
        float4 v0 = in[2 * i], v1 = in[2 * i + 1];
        __half2 h0 = __floats2half2_rn(v0.x, v0.y);
        __half2 h1 = __floats2half2_rn(v0.z, v0.w);
        __half2 h2 = __floats2half2_rn(v1.x, v1.y);
        __half2 h3 = __floats2half2_rn(v1.z, v1.w);
        uint4 o;
        o.x = *(unsigned*)&h0; o.y = *(unsigned*)&h1;
        o.z = *(unsigned*)&h2; o.w = *(unsigned*)&h3;
        *(uint4*)(out + (size_t)8 * i) = o;
    }
}

__device__ __forceinline__ void do_transpose32(const float* W, __half* WT,
                                               int K, int N, int bx, int by) {
    __shared__ float t[32][33];
    const int x = threadIdx.x, y = threadIdx.y;
#pragma unroll
    for (int i = 0; i < 32; i += 8)
        t[y + i][x] = W[(size_t)(by + y + i) * N + bx + x];
    __syncthreads();
#pragma unroll
    for (int i = 0; i < 32; i += 8)
        WT[(size_t)(bx + y + i) * K + by + x] = __float2half_rn(t[x][y + i]);
}

constexpr int TS0 = (512 / 32)  * (2048 / 32);
constexpr int TS1 = (2048 / 32) * (2048 / 32);
constexpr int TS2 = (2048 / 32) * (512 / 32);
constexpr int TS3 = (512 / 32)  * (1024 / 32);
constexpr int TS4 = TS3;
constexpr int TS5 = (1024 / 32) * (512 / 32);
constexpr int TS_TOTAL = TS0 + TS1 + TS2 + TS3 + TS4 + TS5 + TS5;

__global__ void prep_transpose(const float* __restrict__ Wx0,
                               const float* __restrict__ Wx1,
                               const float* __restrict__ Wx2,
                               const float* __restrict__ Wy0,
                               const float* __restrict__ Wy1,
                               __half* __restrict__ scr) {
    int b = blockIdx.x;
    const float* W; __half* WT; int K, N, tx;
    if (b < TS0) {
        W = Wx0; WT = scr + OFF_WX0; K = 512;  N = 2048; tx = 64;
    } else if ((b -= TS0) < TS1) {
        W = Wx1; WT = scr + OFF_WX1; K = 2048; N = 2048; tx = 64;
    } else if ((b -= TS1) < TS2) {
        W = Wx2; WT = scr + OFF_WX2; K = 2048; N = 512;  tx = 16;
    } else if ((b -= TS2) < TS3) {
        W = Wy0; WT = scr + OFF_WY0; K = 512;  N = 1024; tx = 32;
    } else if ((b -= TS3) < TS4) {
        W = Wy0 + (size_t)512 * 1024; WT = scr + OFF_WY0 + (size_t)1024 * 512;
        K = 512;  N = 1024; tx = 32;
    } else if ((b -= TS4) < TS5) {
        W = Wy1; WT = scr + OFF_WY1; K = 1024; N = 512;  tx = 16;
    } else {
        b -= TS5;
        W = Wy1 + (size_t)1024 * 512; WT = scr + OFF_WY1 + (size_t)512 * 1024;
        K = 1024; N = 512;  tx = 16;
    }
    do_transpose32(W, WT, K, N, (b % tx) * 32, (b / tx) * 32);
}

// ---------------------------------------------------------------------------
__device__ __forceinline__ int detect64(const int* tr) {
    int a = 0;
#pragma unroll
    for (int i = 1; i < 64; i += 2) a |= tr[i];
    return (a == 0) ? 1 : 0;
}

__global__ void zero_meta_kernel() {
    if (threadIdx.x < 8) g_meta[threadIdx.x] = 0;
}

__global__ void scatter_kernel(const int* __restrict__ tr) {
    __shared__ int s64;
    if (threadIdx.x == 0) s64 = detect64(tr);
    __syncthreads();
    const int row = blockIdx.x * 256 + threadIdx.x;
    const int t = s64 ? tr[2 * row] : tr[row];
    const unsigned full = 0xffffffffu;
    const unsigned mask0 = __ballot_sync(full, t == 0);
    const int c0 = __popc(mask0);
    int b0 = 0, b1 = 0;
    if ((threadIdx.x & 31) == 0) {
        b0 = atomicAdd(&g_meta[4], c0);
        b1 = atomicAdd(&g_meta[5], 32 - c0);
    }
    b0 = __shfl_sync(full, b0, 0);
    b1 = __shfl_sync(full, b1, 0);
    const unsigned lt = (1u << (threadIdx.x & 31)) - 1u;
    if (t == 0) g_idx0[b0 + __popc(mask0 & lt)] = row;
    else        g_idx1[b1 + __popc((~mask0) & lt)] = row;
}

__global__ void pad_kernel() {
    const int cnt0 = g_meta[4];
    const int cnt1 = g_meta[5];
    const int p0 = (cnt0 + 255) & ~255;
    const int p1 = (cnt1 + 255) & ~255;
    if (threadIdx.x == 0) {
        g_meta[0] = cnt0; g_meta[1] = p0;
        g_meta[2] = cnt1; g_meta[3] = p1;
    }
    const int f0 = (cnt0 > 0) ? g_idx0[0] : 0;
    const int f1 = (cnt1 > 0) ? g_idx1[0] : 0;
    for (int i = cnt0 + threadIdx.x; i < p0; i += 256) g_idx0[i] = f0;
    for (int i = cnt1 + threadIdx.x; i < p1; i += 256) g_idx1[i] = f1;
}

// ---------------------------------------------------------------------------
// fp16 GEMM: C = relu(A[M,K] @ BT[N,K]^T + bias), fp32 accumulate.
// ---------------------------------------------------------------------------
constexpr int A_BYTES = 256 * 64 * 2;
constexpr int B_BYTES = 128 * 64 * 2;
constexpr int STG_BYTES = A_BYTES + B_BYTES;
constexpr int NSTAGE = 4;
constexpr int GEMM_SMEM = NSTAGE * STG_BYTES;

__device__ __forceinline__ void cp16s(uint32_t daddr, const void* src) {
    asm volatile("cp.async.cg.shared.global [%0], [%1], 16;" :: "r"(daddr), "l"(src));
}
__device__ __forceinline__ void cp_commit() {
    asm volatile("cp.async.commit_group;" ::);
}
template <int NN>
__device__ __forceinline__ void cp_wait() {
    asm volatile("cp.async.wait_group %0;" :: "n"(NN));
}
__device__ __forceinline__ void ldmx4(unsigned* r, uint32_t addr) {
    asm volatile("ldmatrix.sync.aligned.m8n8.x4.shared.b16 {%0,%1,%2,%3}, [%4];"
                 : "=r"(r[0]), "=r"(r[1]), "=r"(r[2]), "=r"(r[3]) : "r"(addr));
}
__device__ __forceinline__ void mma16816(float* d, const unsigned* a,
                                         unsigned b0, unsigned b1) {
    asm volatile(
        "mma.sync.aligned.m16n8k16.row.col.f32.f16.f16.f32 "
        "{%0,%1,%2,%3}, {%4,%5,%6,%7}, {%8,%9}, {%0,%1,%2,%3};\n"
        : "+f"(d[0]), "+f"(d[1]), "+f"(d[2]), "+f"(d[3])
        : "r"(a[0]), "r"(a[1]), "r"(a[2]), "r"(a[3]), "r"(b0), "r"(b1));
}

template <bool DUAL, bool IDX, bool DYN>
__global__ void __launch_bounds__(256, 1)
gemm_fp16(const __half* __restrict__ A, const __half* __restrict__ BT,
          const float* __restrict__ bias, __half* __restrict__ C,
          float* __restrict__ C2, const int* __restrict__ idx,
          const int* __restrict__ cap, int N, int K) {
    extern __shared__ char smem[];
    const int tid = threadIdx.x, lane = tid & 31, warp = tid >> 5;
    const int wm = warp & 3, wn = warp >> 2;      // 4 warps M x 2 warps N
    const int m0 = blockIdx.y * 256, n0 = blockIdx.x * 128;
    if (DYN) { if (m0 >= __ldg(cap)) return; }

    const uint32_t sb = (uint32_t)__cvta_generic_to_shared(smem);

    // producer state, base+stride form (rows step by 32; r&7 phase invariant)
    const int pr = tid >> 3;                 // base row 0..31
    const int pk = tid & 7;                  // 16B chunk in row
    const uint32_t pswz = (uint32_t)(pr * 128 + ((pk ^ (pr & 7)) << 4));
    const __half* aptr0;
    int arowi[8];
    if (IDX) {
#pragma unroll
        for (int i = 0; i < 8; i++) arowi[i] = __ldg(idx + m0 + pr + i * 32);
        aptr0 = A + (size_t)pk * 8;
    } else {
        aptr0 = A + (size_t)(m0 + pr) * K + pk * 8;
    }
    const __half* bptr0 = BT + (size_t)(n0 + pr) * K + pk * 8;

    float acc[4][8][4];
#pragma unroll
    for (int i = 0; i < 4; i++)
#pragma unroll
        for (int j = 0; j < 8; j++)
#pragma unroll
            for (int q = 0; q < 4; q++) acc[i][j][q] = 0.f;

    auto load_tiles = [&](int kt) {
        const int k0 = kt * 64;
        const uint32_t bb = sb + (uint32_t)(kt & (NSTAGE - 1)) * STG_BYTES + pswz;
        if (IDX) {
#pragma unroll
            for (int i = 0; i < 8; i++)
                cp16s(bb + i * 4096, aptr0 + (size_t)arowi[i] * K + k0);
        } else {
#pragma unroll
            for (int i = 0; i < 8; i++)
                cp16s(bb + i * 4096, aptr0 + (size_t)i * 32 * K + k0);
        }
#pragma unroll
        for (int i = 0; i < 4; i++)
            cp16s(bb + A_BYTES + i * 4096, bptr0 + (size_t)i * 32 * K + k0);
        cp_commit();
    };

    const int nk = K / 64;
    load_tiles(0); load_tiles(1); load_tiles(2);

    // consumer ldmatrix address components
    const int lrow = lane & 7;
    const int g8 = (lane >> 3) & 1;
    const int kg = lane >> 4;
    const uint32_t aoffs = (uint32_t)((wm * 64 + g8 * 8 + lrow) * 128);
    const uint32_t boffs = (uint32_t)(A_BYTES + (wn * 64 + g8 * 8 + lrow) * 128);

    unsigned af[2][4][4], bf[2][4][4];

    auto load_frags = [&](int ks, uint32_t st, unsigned a[4][4], unsigned b[4][4]) {
        const uint32_t kxo = (uint32_t)(((ks * 2 + kg) ^ lrow) << 4);
#pragma unroll
        for (int mt = 0; mt < 4; ++mt) ldmx4(a[mt], st + aoffs + mt * 2048 + kxo);
#pragma unroll
        for (int np = 0; np < 4; ++np) ldmx4(b[np], st + boffs + np * 2048 + kxo);
    };
    auto compute = [&](unsigned a[4][4], unsigned b[4][4]) {
#pragma unroll
        for (int mt = 0; mt < 4; ++mt)
#pragma unroll
            for (int np = 0; np < 4; ++np) {
                mma16816(acc[mt][2 * np],     a[mt], b[np][0], b[np][2]);
                mma16816(acc[mt][2 * np + 1], a[mt], b[np][1], b[np][3]);
            }
    };

    for (int kt = 0; kt < nk; ++kt) {
        cp_wait<2>();
        __syncthreads();
        if (kt + 3 < nk) load_tiles(kt + 3);
        else cp_commit();

        const uint32_t st = sb + (uint32_t)(kt & (NSTAGE - 1)) * STG_BYTES;
        load_frags(0, st, af[0], bf[0]);
#pragma unroll
        for (int ks = 0; ks < 4; ++ks) {
            if (ks < 3) load_frags(ks + 1, st, af[(ks + 1) & 1], bf[(ks + 1) & 1]);
            compute(af[ks & 1], bf[ks & 1]);
        }
    }

    // epilogue: +bias, ReLU, fp16 store (+ optional fp32 dual store)
#pragma unroll
    for (int nt = 0; nt < 8; ++nt) {
        const int col = n0 + wn * 64 + nt * 8 + 2 * (lane & 3);
        const float b0v = bias[col], b1v = bias[col + 1];
#pragma unroll
        for (int mt = 0; mt < 4; ++mt) {
            const int row = m0 + wm * 64 + mt * 16 + (lane >> 2);
            const float v0 = fmaxf(acc[mt][nt][0] + b0v, 0.f);
            const float v1 = fmaxf(acc[mt][nt][1] + b1v, 0.f);
            const float v2 = fmaxf(acc[mt][nt][2] + b0v, 0.f);
            const float v3 = fmaxf(acc[mt][nt][3] + b1v, 0.f);
            const size_t o0 = (size_t)row * N + col;
            const size_t o1 = (size_t)(row + 8) * N + col;
            if (DUAL) {
                *(float2*)(C2 + o0) = make_float2(v0, v1);
                *(float2*)(C2 + o1) = make_float2(v2, v3);
            }
            *(__half2*)(C + o0) = __floats2half2_rn(v0, v1);
            *(__half2*)(C + o1) = __floats2half2_rn(v2, v3);
        }
    }
}

// ---------------------------------------------------------------------------
__global__ void head_kernel(const int* __restrict__ idx,
                            const int* __restrict__ cnt_ptr,
                            const __half* __restrict__ G1,
                            const float* __restrict__ Wo,
                            const float* __restrict__ bo,
                            float* __restrict__ y, float* __restrict__ tout) {
    const int cnt = __ldg(cnt_ptr);
    const int slot = blockIdx.x * 8 + (threadIdx.x >> 5);
    if (slot >= cnt) return;
    const int lane = threadIdx.x & 31;
    const __half* g = G1 + (size_t)slot * 512;
    float s = 0.f;
#pragma unroll
    for (int j = 0; j < 2; j++) {
        const int base = j * 256 + lane * 8;
        uint4 gv = *(const uint4*)(g + base);
        float4 w0 = *(const float4*)(Wo + base);
        float4 w1 = *(const float4*)(Wo + base + 4);
        float2 f0 = __half22float2(*(__half2*)&gv.x);
        float2 f1 = __half22float2(*(__half2*)&gv.y);
        float2 f2 = __half22float2(*(__half2*)&gv.z);
        float2 f3 = __half22float2(*(__half2*)&gv.w);
        s += f0.x * w0.x + f0.y * w0.y + f1.x * w0.z + f1.y * w0.w;
        s += f2.x * w1.x + f2.y * w1.y + f3.x * w1.z + f3.y * w1.w;
    }
#pragma unroll
    for (int o = 16; o > 0; o >>= 1) s += __shfl_xor_sync(0xffffffffu, s, o);
    if (lane == 0) {
        const int orig = idx[slot];
        y[orig]    = s + bo[0];
        tout[orig] = 1.0f;
    }
}

// ---------------------------------------------------------------------------
extern "C" void kernel_launch(void* const* d_in, const int* in_sizes, int n_in,
                              void* d_out, int out_size) {
    const float* x   = (const float*)d_in[0];
    const int*   tr  = (const int*)  d_in[1];
    const float* Wx0 = (const float*)d_in[2];
    const float* bx0 = (const float*)d_in[3];
    const float* Wx1 = (const float*)d_in[4];
    const float* bx1 = (const float*)d_in[5];
    const float* Wx2 = (const float*)d_in[6];
    const float* bx2 = (const float*)d_in[7];
    const float* Wy0 = (const float*)d_in[8];
    const float* by0 = (const float*)d_in[9];
    const float* Wy1 = (const float*)d_in[10];
    const float* by1 = (const float*)d_in[11];
    const float* Wo  = (const float*)d_in[12];
    const float* bo  = (const float*)d_in[13];
    // Wt/bt dead: softmax over size-1 axis == 1.

    float* out  = (float*)d_out;
    float* y    = out;
    float* xemb = out + NROWS;
    float* tout = out + NROWS + (size_t)NROWS * 512;

    __half* scr = nullptr;
    cudaGetSymbolAddress((void**)&scr, g_scratch);
    int* idx0 = nullptr; cudaGetSymbolAddress((void**)&idx0, g_idx0);
    int* idx1 = nullptr; cudaGetSymbolAddress((void**)&idx1, g_idx1);
    int* meta = nullptr; cudaGetSymbolAddress((void**)&meta, g_meta);

    __half* Xh   = scr + OFF_XH;
    __half* WX0T = scr + OFF_WX0;
    __half* WX1T = scr + OFF_WX1;
    __half* WX2T = scr + OFF_WX2;
    __half* WY0T = scr + OFF_WY0;
    __half* WY1T = scr + OFF_WY1;
    __half* H0   = scr + OFF_H0;
    __half* H1   = scr + OFF_H1;
    __half* XEh  = scr + OFF_XEH;
    __half* G0a  = scr + OFF_G0A;
    __half* G0b  = scr + OFF_G0B;
    __half* G1a  = scr + OFF_G1A;
    __half* G1b  = scr + OFF_G1B;

    cudaFuncSetAttribute(gemm_fp16<false, false, false>,
                         cudaFuncAttributeMaxDynamicSharedMemorySize, GEMM_SMEM);
    cudaFuncSetAttribute(gemm_fp16<true,  false, false>,
                         cudaFuncAttributeMaxDynamicSharedMemorySize, GEMM_SMEM);
    cudaFuncSetAttribute(gemm_fp16<false, true,  true>,
                         cudaFuncAttributeMaxDynamicSharedMemorySize, GEMM_SMEM);
    cudaFuncSetAttribute(gemm_fp16<false, false, true>,
                         cudaFuncAttributeMaxDynamicSharedMemorySize, GEMM_SMEM);

    const dim3 blk(256);
    const int MT = NROWS / 256;

    // launch order: trunk GEMM2 is index 3 (the launch ncu profiles)
    {
        int n8 = (int)((size_t)NROWS * 512 / 8);
        cvt_half_kernel<<<(n8 + 255) / 256, 256>>>((const float4*)x, Xh, n8);   // 0
    }
    prep_transpose<<<TS_TOTAL, dim3(32, 8)>>>(Wx0, Wx1, Wx2, Wy0, Wy1, scr);    // 1

    gemm_fp16<false, false, false><<<dim3(2048 / 128, MT), blk, GEMM_SMEM>>>(   // 2
        Xh, WX0T, bx0, H0, nullptr, nullptr, nullptr, 2048, 512);
    gemm_fp16<false, false, false><<<dim3(2048 / 128, MT), blk, GEMM_SMEM>>>(   // 3
        H0, WX1T, bx1, H1, nullptr, nullptr, nullptr, 2048, 2048);

    zero_meta_kernel<<<1, 32>>>();                                              // 4
    scatter_kernel<<<NROWS / 256, 256>>>(tr);                                   // 5
    pad_kernel<<<1, 256>>>();                                                   // 6

    gemm_fp16<true, false, false><<<dim3(512 / 128, MT), blk, GEMM_SMEM>>>(     // 7
        H1, WX2T, bx2, XEh, xemb, nullptr, nullptr, 512, 2048);

    gemm_fp16<false, true, true><<<dim3(1024 / 128, MT), blk, GEMM_SMEM>>>(
        XEh, WY0T, by0, G0a, nullptr, idx0, meta + 1, 1024, 512);
    gemm_fp16<false, true, true><<<dim3(1024 / 128, MT), blk, GEMM_SMEM>>>(
        XEh, WY0T + (size_t)1024 * 512, by0 + 1024, G0b, nullptr, idx1, meta + 3, 1024, 512);
    gemm_fp16<false, false, true><<<dim3(512 / 128, MT), blk, GEMM_SMEM>>>(
        G0a, WY1T, by1, G1a, nullptr, nullptr, meta + 1, 512, 1024);
    gemm_fp16<false, false, true><<<dim3(512 / 128, MT), blk, GEMM_SMEM>>>(
        G0b, WY1T + (size_t)512 * 1024, by1 + 512, G1b, nullptr, nullptr, meta + 3, 512, 1024);

    head_kernel<<<NROWS / 8, 256>>>(idx0, meta + 0, G1a, Wo,       bo,     y, tout);
    head_kernel<<<NROWS / 8, 256>>>(idx1, meta + 2, G1b, Wo + 512, bo + 1, y, tout);
}

// round 7
// speedup vs baseline: 1.0824x; 1.0824x over previous
#include <cuda_runtime.h>
#include <cuda_fp16.h>
#include <cstdint>
#include <cstddef>

// ---------------------------------------------------------------------------
// DeepCausalModel. fp16 mma.m16n8k16 path (tcgen05 blocked by compute_103).
// R6 ncu: tensor=61.7%, occ=12.4% (1 CTA/SM) -> barrier bubbles unfillable.
// R7: CTA 128x128, warp 64x32, 3-stage cp.async, 2 CTAs/SM for overlap.
// Experts gathered by treatment.
// ---------------------------------------------------------------------------

#define NROWS 65536

constexpr size_t OFF_XH  = 0;                                // [N,512]
constexpr size_t OFF_WX0 = OFF_XH  + (size_t)NROWS * 512;    // [2048,512] (T)
constexpr size_t OFF_WX1 = OFF_WX0 + (size_t)512 * 2048;     // [2048,2048]
constexpr size_t OFF_WX2 = OFF_WX1 + (size_t)2048 * 2048;    // [512,2048]
constexpr size_t OFF_WY0 = OFF_WX2 + (size_t)2048 * 512;     // 2x [1024,512]
constexpr size_t OFF_WY1 = OFF_WY0 + (size_t)2 * 512 * 1024; // 2x [512,1024]
constexpr size_t OFF_H0  = OFF_WY1 + (size_t)2 * 1024 * 512; // [N,2048]
constexpr size_t OFF_H1  = OFF_H0  + (size_t)NROWS * 2048;   // [N,2048]
constexpr size_t OFF_XEH = OFF_H1  + (size_t)NROWS * 2048;   // [N,512]
constexpr size_t SCR_TOTAL = OFF_XEH + (size_t)NROWS * 512;
constexpr size_t OFF_G0A = OFF_H0;
constexpr size_t OFF_G0B = OFF_H0 + (size_t)NROWS * 1024;
constexpr size_t OFF_G1A = OFF_H1;
constexpr size_t OFF_G1B = OFF_H1 + (size_t)NROWS * 512;

__device__ __half g_scratch[SCR_TOTAL];
__device__ int    g_idx0[NROWS];
__device__ int    g_idx1[NROWS];
__device__ int    g_meta[8];

// ---------------------------------------------------------------------------
__global__ void cvt_half_kernel(const float4* __restrict__ in,
                                __half* __restrict__ out, int n8) {
    int i = blockIdx.x * blockDim.x + threadIdx.x;
    if (i < n8) {
        float4 v0 = in[2 * i], v1 = in[2 * i + 1];
        __half2 h0 = __floats2half2_rn(v0.x, v0.y);
        __half2 h1 = __floats2half2_rn(v0.z, v0.w);
        __half2 h2 = __floats2half2_rn(v1.x, v1.y);
        __half2 h3 = __floats2half2_rn(v1.z, v1.w);
        uint4 o;
        o.x = *(unsigned*)&h0; o.y = *(unsigned*)&h1;
        o.z = *(unsigned*)&h2; o.w = *(unsigned*)&h3;
        *(uint4*)(out + (size_t)8 * i) = o;
    }
}

__device__ __forceinline__ void do_transpose32(const float* W, __half* WT,
                                               int K, int N, int bx, int by) {
    __shared__ float t[32][33];
    const int x = threadIdx.x, y = threadIdx.y;
#pragma unroll
    for (int i = 0; i < 32; i += 8)
        t[y + i][x] = W[(size_t)(by + y + i) * N + bx + x];
    __syncthreads();
#pragma unroll
    for (int i = 0; i < 32; i += 8)
        WT[(size_t)(bx + y + i) * K + by + x] = __float2half_rn(t[x][y + i]);
}

constexpr int TS0 = (512 / 32)  * (2048 / 32);
constexpr int TS1 = (2048 / 32) * (2048 / 32);
constexpr int TS2 = (2048 / 32) * (512 / 32);
constexpr int TS3 = (512 / 32)  * (1024 / 32);
constexpr int TS4 = TS3;
constexpr int TS5 = (1024 / 32) * (512 / 32);
constexpr int TS_TOTAL = TS0 + TS1 + TS2 + TS3 + TS4 + TS5 + TS5;

__global__ void prep_transpose(const float* __restrict__ Wx0,
                               const float* __restrict__ Wx1,
                               const float* __restrict__ Wx2,
                               const float* __restrict__ Wy0,
                               const float* __restrict__ Wy1,
                               __half* __restrict__ scr) {
    int b = blockIdx.x;
    const float* W; __half* WT; int K, N, tx;
    if (b < TS0) {
        W = Wx0; WT = scr + OFF_WX0; K = 512;  N = 2048; tx = 64;
    } else if ((b -= TS0) < TS1) {
        W = Wx1; WT = scr + OFF_WX1; K = 2048; N = 2048; tx = 64;
    } else if ((b -= TS1) < TS2) {
        W = Wx2; WT = scr + OFF_WX2; K = 2048; N = 512;  tx = 16;
    } else if ((b -= TS2) < TS3) {
        W = Wy0; WT = scr + OFF_WY0; K = 512;  N = 1024; tx = 32;
    } else if ((b -= TS3) < TS4) {
        W = Wy0 + (size_t)512 * 1024; WT = scr + OFF_WY0 + (size_t)1024 * 512;
        K = 512;  N = 1024; tx = 32;
    } else if ((b -= TS4) < TS5) {
        W = Wy1; WT = scr + OFF_WY1; K = 1024; N = 512;  tx = 16;
    } else {
        b -= TS5;
        W = Wy1 + (size_t)1024 * 512; WT = scr + OFF_WY1 + (size_t)512 * 1024;
        K = 1024; N = 512;  tx = 16;
    }
    do_transpose32(W, WT, K, N, (b % tx) * 32, (b / tx) * 32);
}

// ---------------------------------------------------------------------------
__device__ __forceinline__ int detect64(const int* tr) {
    int a = 0;
#pragma unroll
    for (int i = 1; i < 64; i += 2) a |= tr[i];
    return (a == 0) ? 1 : 0;
}

__global__ void zero_meta_kernel() {
    if (threadIdx.x < 8) g_meta[threadIdx.x] = 0;
}

__global__ void scatter_kernel(const int* __restrict__ tr) {
    __shared__ int s64;
    if (threadIdx.x == 0) s64 = detect64(tr);
    __syncthreads();
    const int row = blockIdx.x * 256 + threadIdx.x;
    const int t = s64 ? tr[2 * row] : tr[row];
    const unsigned full = 0xffffffffu;
    const unsigned mask0 = __ballot_sync(full, t == 0);
    const int c0 = __popc(mask0);
    int b0 = 0, b1 = 0;
    if ((threadIdx.x & 31) == 0) {
        b0 = atomicAdd(&g_meta[4], c0);
        b1 = atomicAdd(&g_meta[5], 32 - c0);
    }
    b0 = __shfl_sync(full, b0, 0);
    b1 = __shfl_sync(full, b1, 0);
    const unsigned lt = (1u << (threadIdx.x & 31)) - 1u;
    if (t == 0) g_idx0[b0 + __popc(mask0 & lt)] = row;
    else        g_idx1[b1 + __popc((~mask0) & lt)] = row;
}

__global__ void pad_kernel() {
    const int cnt0 = g_meta[4];
    const int cnt1 = g_meta[5];
    const int p0 = (cnt0 + 255) & ~255;
    const int p1 = (cnt1 + 255) & ~255;
    if (threadIdx.x == 0) {
        g_meta[0] = cnt0; g_meta[1] = p0;
        g_meta[2] = cnt1; g_meta[3] = p1;
    }
    const int f0 = (cnt0 > 0) ? g_idx0[0] : 0;
    const int f1 = (cnt1 > 0) ? g_idx1[0] : 0;
    for (int i = cnt0 + threadIdx.x; i < p0; i += 256) g_idx0[i] = f0;
    for (int i = cnt1 + threadIdx.x; i < p1; i += 256) g_idx1[i] = f1;
}

// ---------------------------------------------------------------------------
// fp16 GEMM: C = relu(A[M,K] @ BT[N,K]^T + bias), fp32 accumulate.
// CTA 128x128, warp 64x32 (2 warps M x 4 warps N), BK=64, 3 stages.
// ---------------------------------------------------------------------------
constexpr int A_BYTES = 128 * 64 * 2;        // 16384
constexpr int B_BYTES = 128 * 64 * 2;        // 16384
constexpr int STG_BYTES = A_BYTES + B_BYTES; // 32768
constexpr int NSTAGE = 3;
constexpr int GEMM_SMEM = NSTAGE * STG_BYTES;  // 98304 (2 CTAs/SM)

__device__ __forceinline__ void cp16s(uint32_t daddr, const void* src) {
    asm volatile("cp.async.cg.shared.global [%0], [%1], 16;" :: "r"(daddr), "l"(src));
}
__device__ __forceinline__ void cp_commit() {
    asm volatile("cp.async.commit_group;" ::);
}
template <int NN>
__device__ __forceinline__ void cp_wait() {
    asm volatile("cp.async.wait_group %0;" :: "n"(NN));
}
__device__ __forceinline__ void ldmx4(unsigned* r, uint32_t addr) {
    asm volatile("ldmatrix.sync.aligned.m8n8.x4.shared.b16 {%0,%1,%2,%3}, [%4];"
                 : "=r"(r[0]), "=r"(r[1]), "=r"(r[2]), "=r"(r[3]) : "r"(addr));
}
__device__ __forceinline__ void mma16816(float* d, const unsigned* a,
                                         unsigned b0, unsigned b1) {
    asm volatile(
        "mma.sync.aligned.m16n8k16.row.col.f32.f16.f16.f32 "
        "{%0,%1,%2,%3}, {%4,%5,%6,%7}, {%8,%9}, {%0,%1,%2,%3};\n"
        : "+f"(d[0]), "+f"(d[1]), "+f"(d[2]), "+f"(d[3])
        : "r"(a[0]), "r"(a[1]), "r"(a[2]), "r"(a[3]), "r"(b0), "r"(b1));
}

template <bool DUAL, bool IDX, bool DYN>
__global__ void __launch_bounds__(256, 2)
gemm_fp16(const __half* __restrict__ A, const __half* __restrict__ BT,
          const float* __restrict__ bias, __half* __restrict__ C,
          float* __restrict__ C2, const int* __restrict__ idx,
          const int* __restrict__ cap, int N, int K) {
    extern __shared__ char smem[];
    const int tid = threadIdx.x, lane = tid & 31, warp = tid >> 5;
    const int wm = warp & 1, wn = warp >> 1;      // 2 warps M x 4 warps N
    const int m0 = blockIdx.y * 128, n0 = blockIdx.x * 128;
    if (DYN) { if (m0 >= __ldg(cap)) return; }

    const uint32_t sb = (uint32_t)__cvta_generic_to_shared(smem);

    // producer: 256 threads, A 1024 chunks (4/thread), B 1024 chunks (4/thread)
    const int pr = tid >> 3;                 // base row 0..31 (step 32)
    const int pk = tid & 7;                  // 16B chunk in row
    const uint32_t pswz = (uint32_t)(pr * 128 + ((pk ^ (pr & 7)) << 4));
    const __half* aptr0;
    int arowi[4];
    if (IDX) {
#pragma unroll
        for (int i = 0; i < 4; i++) arowi[i] = __ldg(idx + m0 + pr + i * 32);
        aptr0 = A + (size_t)pk * 8;
    } else {
        aptr0 = A + (size_t)(m0 + pr) * K + pk * 8;
    }
    const __half* bptr0 = BT + (size_t)(n0 + pr) * K + pk * 8;

    float acc[4][4][4];
#pragma unroll
    for (int i = 0; i < 4; i++)
#pragma unroll
        for (int j = 0; j < 4; j++)
#pragma unroll
            for (int q = 0; q < 4; q++) acc[i][j][q] = 0.f;

    auto load_tiles = [&](int kt) {
        const int k0 = kt * 64;
        int s = kt; while (s >= NSTAGE) s -= NSTAGE;
        const uint32_t bb = sb + (uint32_t)s * STG_BYTES + pswz;
        if (IDX) {
#pragma unroll
            for (int i = 0; i < 4; i++)
                cp16s(bb + i * 4096, aptr0 + (size_t)arowi[i] * K + k0);
        } else {
#pragma unroll
            for (int i = 0; i < 4; i++)
                cp16s(bb + i * 4096, aptr0 + (size_t)i * 32 * K + k0);
        }
#pragma unroll
        for (int i = 0; i < 4; i++)
            cp16s(bb + A_BYTES + i * 4096, bptr0 + (size_t)i * 32 * K + k0);
        cp_commit();
    };

    const int nk = K / 64;
    load_tiles(0); load_tiles(1);

    // consumer ldmatrix address components
    const int lrow = lane & 7;
    const int g8 = (lane >> 3) & 1;
    const int kg = lane >> 4;
    const uint32_t aoffs = (uint32_t)((wm * 64 + g8 * 8 + lrow) * 128);
    const uint32_t boffs = (uint32_t)(A_BYTES + (wn * 32 + g8 * 8 + lrow) * 128);

    int stg = 0;
    for (int kt = 0; kt < nk; ++kt) {
        cp_wait<1>();
        __syncthreads();
        if (kt + 2 < nk) load_tiles(kt + 2);
        else cp_commit();

        const uint32_t st = sb + (uint32_t)stg * STG_BYTES;
        if (++stg == NSTAGE) stg = 0;
#pragma unroll
        for (int ks = 0; ks < 4; ++ks) {
            const uint32_t kxo = (uint32_t)(((ks * 2 + kg) ^ lrow) << 4);
            unsigned a[4][4];
#pragma unroll
            for (int mt = 0; mt < 4; ++mt)
                ldmx4(a[mt], st + aoffs + mt * 2048 + kxo);
            unsigned b[2][4];
#pragma unroll
            for (int np = 0; np < 2; ++np)
                ldmx4(b[np], st + boffs + np * 2048 + kxo);
#pragma unroll
            for (int mt = 0; mt < 4; ++mt)
#pragma unroll
                for (int np = 0; np < 2; ++np) {
                    mma16816(acc[mt][2 * np],     a[mt], b[np][0], b[np][2]);
                    mma16816(acc[mt][2 * np + 1], a[mt], b[np][1], b[np][3]);
                }
        }
    }

    // epilogue: +bias, ReLU, fp16 store (+ optional fp32 dual store)
#pragma unroll
    for (int nt = 0; nt < 4; ++nt) {
        const int col = n0 + wn * 32 + nt * 8 + 2 * (lane & 3);
        const float b0v = bias[col], b1v = bias[col + 1];
#pragma unroll
        for (int mt = 0; mt < 4; ++mt) {
            const int row = m0 + wm * 64 + mt * 16 + (lane >> 2);
            const float v0 = fmaxf(acc[mt][nt][0] + b0v, 0.f);
            const float v1 = fmaxf(acc[mt][nt][1] + b1v, 0.f);
            const float v2 = fmaxf(acc[mt][nt][2] + b0v, 0.f);
            const float v3 = fmaxf(acc[mt][nt][3] + b1v, 0.f);
            const size_t o0 = (size_t)row * N + col;
            const size_t o1 = (size_t)(row + 8) * N + col;
            if (DUAL) {
                *(float2*)(C2 + o0) = make_float2(v0, v1);
                *(float2*)(C2 + o1) = make_float2(v2, v3);
            }
            *(__half2*)(C + o0) = __floats2half2_rn(v0, v1);
            *(__half2*)(C + o1) = __floats2half2_rn(v2, v3);
        }
    }
}

// ---------------------------------------------------------------------------
__global__ void head_kernel(const int* __restrict__ idx,
                            const int* __restrict__ cnt_ptr,
                            const __half* __restrict__ G1,
                            const float* __restrict__ Wo,
                            const float* __restrict__ bo,
                            float* __restrict__ y, float* __restrict__ tout) {
    const int cnt = __ldg(cnt_ptr);
    const int slot = blockIdx.x * 8 + (threadIdx.x >> 5);
    if (slot >= cnt) return;
    const int lane = threadIdx.x & 31;
    const __half* g = G1 + (size_t)slot * 512;
    float s = 0.f;
#pragma unroll
    for (int j = 0; j < 2; j++) {
        const int base = j * 256 + lane * 8;
        uint4 gv = *(const uint4*)(g + base);
        float4 w0 = *(const float4*)(Wo + base);
        float4 w1 = *(const float4*)(Wo + base + 4);
        float2 f0 = __half22float2(*(__half2*)&gv.x);
        float2 f1 = __half22float2(*(__half2*)&gv.y);
        float2 f2 = __half22float2(*(__half2*)&gv.z);
        float2 f3 = __half22float2(*(__half2*)&gv.w);
        s += f0.x * w0.x + f0.y * w0.y + f1.x * w0.z + f1.y * w0.w;
        s += f2.x * w1.x + f2.y * w1.y + f3.x * w1.z + f3.y * w1.w;
    }
#pragma unroll
    for (int o = 16; o > 0; o >>= 1) s += __shfl_xor_sync(0xffffffffu, s, o);
    if (lane == 0) {
        const int orig = idx[slot];
        y[orig]    = s + bo[0];
        tout[orig] = 1.0f;
    }
}

// ---------------------------------------------------------------------------
extern "C" void kernel_launch(void* const* d_in, const int* in_sizes, int n_in,
                              void* d_out, int out_size) {
    const float* x   = (const float*)d_in[0];
    const int*   tr  = (const int*)  d_in[1];
    const float* Wx0 = (const float*)d_in[2];
    const float* bx0 = (const float*)d_in[3];
    const float* Wx1 = (const float*)d_in[4];
    const float* bx1 = (const float*)d_in[5];
    const float* Wx2 = (const float*)d_in[6];
    const float* bx2 = (const float*)d_in[7];
    const float* Wy0 = (const float*)d_in[8];
    const float* by0 = (const float*)d_in[9];
    const float* Wy1 = (const float*)d_in[10];
    const float* by1 = (const float*)d_in[11];
    const float* Wo  = (const float*)d_in[12];
    const float* bo  = (const float*)d_in[13];
    // Wt/bt dead: softmax over size-1 axis == 1.

    float* out  = (float*)d_out;
    float* y    = out;
    float* xemb = out + NROWS;
    float* tout = out + NROWS + (size_t)NROWS * 512;

    __half* scr = nullptr;
    cudaGetSymbolAddress((void**)&scr, g_scratch);
    int* idx0 = nullptr; cudaGetSymbolAddress((void**)&idx0, g_idx0);
    int* idx1 = nullptr; cudaGetSymbolAddress((void**)&idx1, g_idx1);
    int* meta = nullptr; cudaGetSymbolAddress((void**)&meta, g_meta);

    __half* Xh   = scr + OFF_XH;
    __half* WX0T = scr + OFF_WX0;
    __half* WX1T = scr + OFF_WX1;
    __half* WX2T = scr + OFF_WX2;
    __half* WY0T = scr + OFF_WY0;
    __half* WY1T = scr + OFF_WY1;
    __half* H0   = scr + OFF_H0;
    __half* H1   = scr + OFF_H1;
    __half* XEh  = scr + OFF_XEH;
    __half* G0a  = scr + OFF_G0A;
    __half* G0b  = scr + OFF_G0B;
    __half* G1a  = scr + OFF_G1A;
    __half* G1b  = scr + OFF_G1B;

    cudaFuncSetAttribute(gemm_fp16<false, false, false>,
                         cudaFuncAttributeMaxDynamicSharedMemorySize, GEMM_SMEM);
    cudaFuncSetAttribute(gemm_fp16<true,  false, false>,
                         cudaFuncAttributeMaxDynamicSharedMemorySize, GEMM_SMEM);
    cudaFuncSetAttribute(gemm_fp16<false, true,  true>,
                         cudaFuncAttributeMaxDynamicSharedMemorySize, GEMM_SMEM);
    cudaFuncSetAttribute(gemm_fp16<false, false, true>,
                         cudaFuncAttributeMaxDynamicSharedMemorySize, GEMM_SMEM);

    const dim3 blk(256);
    const int MT = NROWS / 128;  // 512 m-tiles

    // launch order: trunk GEMM2 is index 3 (the launch ncu profiles)
    {
        int n8 = (int)((size_t)NROWS * 512 / 8);
        cvt_half_kernel<<<(n8 + 255) / 256, 256>>>((const float4*)x, Xh, n8);   // 0
    }
    prep_transpose<<<TS_TOTAL, dim3(32, 8)>>>(Wx0, Wx1, Wx2, Wy0, Wy1, scr);    // 1

    gemm_fp16<false, false, false><<<dim3(2048 / 128, MT), blk, GEMM_SMEM>>>(   // 2
        Xh, WX0T, bx0, H0, nullptr, nullptr, nullptr, 2048, 512);
    gemm_fp16<false, false, false><<<dim3(2048 / 128, MT), blk, GEMM_SMEM>>>(   // 3
        H0, WX1T, bx1, H1, nullptr, nullptr, nullptr, 2048, 2048);

    zero_meta_kernel<<<1, 32>>>();                                              // 4
    scatter_kernel<<<NROWS / 256, 256>>>(tr);                                   // 5
    pad_kernel<<<1, 256>>>();                                                   // 6

    gemm_fp16<true, false, false><<<dim3(512 / 128, MT), blk, GEMM_SMEM>>>(     // 7
        H1, WX2T, bx2, XEh, xemb, nullptr, nullptr, 512, 2048);

    gemm_fp16<false, true, true><<<dim3(1024 / 128, MT), blk, GEMM_SMEM>>>(
        XEh, WY0T, by0, G0a, nullptr, idx0, meta + 1, 1024, 512);
    gemm_fp16<false, true, true><<<dim3(1024 / 128, MT), blk, GEMM_SMEM>>>(
        XEh, WY0T + (size_t)1024 * 512, by0 + 1024, G0b, nullptr, idx1, meta + 3, 1024, 512);
    gemm_fp16<false, false, true><<<dim3(512 / 128, MT), blk, GEMM_SMEM>>>(
        G0a, WY1T, by1, G1a, nullptr, nullptr, meta + 1, 512, 1024);
    gemm_fp16<false, false, true><<<dim3(512 / 128, MT), blk, GEMM_SMEM>>>(
        G0b, WY1T + (size_t)512 * 1024, by1 + 512, G1b, nullptr, nullptr, meta + 3, 512, 1024);

    head_kernel<<<NROWS / 8, 256>>>(idx0, meta + 0, G1a, Wo,       bo,     y, tout);
    head_kernel<<<NROWS / 8, 256>>>(idx1, meta + 2, G1b, Wo + 512, bo + 1, y, tout);
}